// round 2
// baseline (speedup 1.0000x reference)
#include <cuda_runtime.h>
#include <cuda_bf16.h>
#include <cstdint>

// Problem constants (shapes are fixed by the dataset)
#define BATCH   64
#define MAXH    64
#define MAXW    32
#define DIM     512
#define SGRID   8
#define HID     64

// CTA tiling: 64 points (1 batch, 2 i-rows, 32 j) x all 512 d
// 256 threads: warp my in [0,8), lane nx in [0,32)
// thread tile: 8 points x 8 d-pairs (16 d, strided), packed f32x2 accumulation
#define TPB         256
#define PTS_PER_CTA 64
#define NTILES      (BATCH * MAXH * MAXW / PTS_PER_CTA)   // 2048

// Dynamic SMEM: h duplicated as float2 {h,h}: 64 pts * 64 k * 8B = 32768
//               w2 fp32: 64 * 512 * 4 = 131072
#define SH_H_BYTES  (PTS_PER_CTA * HID * 8)
#define SH_W2_BYTES (HID * DIM * 4)
#define SMEM_BYTES  (SH_H_BYTES + SH_W2_BYTES)            // 163840 < 227KB cap

__device__ __forceinline__ float gelu_exact(float x) {
    // jax.nn.gelu(approximate=False): 0.5*x*(1+erf(x/sqrt(2)))
    return 0.5f * x * (1.0f + erff(x * 0.70710678118654752440f));
}

__global__ __launch_bounds__(TPB) void hgq_main(
    const float* __restrict__ canonical,  // [8,8,512]
    const float* __restrict__ w1,         // [2,64]
    const float* __restrict__ b1,         // [64]
    const float* __restrict__ w2,         // [64,512]
    const float* __restrict__ b2,         // [512]
    const int*   __restrict__ th,         // [64]
    const int*   __restrict__ tw,         // [64]
    float*       __restrict__ out)        // [64,64,32,512]
{
    extern __shared__ char smem[];
    float2* sh_h = (float2*)smem;                         // [64 pts][64 k] as {h,h}
    float*  sh_w2 = (float*)(smem + SH_H_BYTES);          // [64 k][512 d]

    const int tid  = threadIdx.x;
    const int tile = blockIdx.x;          // 0..2047
    const int bb   = tile >> 5;           // batch index (32 tiles per batch)
    const int i0   = (tile & 31) << 1;    // first of 2 i rows

    const int H = min(max(th[bb], 1), MAXH);
    const int W = min(max(tw[bb], 1), MAXW);

    // ---- stage w2 into SMEM (vectorized, coalesced) ----
    {
        const float4* w2v = (const float4*)w2;
        float4* sw = (float4*)sh_w2;
        #pragma unroll
        for (int t = 0; t < (HID * DIM / 4) / TPB; t++)   // 32 iters
            sw[tid + TPB * t] = w2v[tid + TPB * t];
    }

    // ---- build h = gelu(u*w1[0,k] + v*w1[1,k] + b1[k]) for 64 points ----
    {
        #pragma unroll
        for (int t = 0; t < (PTS_PER_CTA * HID) / TPB; t++) {  // 16 iters
            int idx = tid + TPB * t;
            int p = idx >> 6;             // local point 0..63
            int k = idx & 63;
            int i = i0 + (p >> 5);
            int j = p & 31;
            float u = (H > 1) ? (float)i / (float)(H - 1) : 0.0f;
            float v = (W > 1) ? (float)j / (float)(W - 1) : 0.0f;
            float x = u * w1[k] + v * w1[HID + k] + b1[k];
            float g = gelu_exact(x);
            sh_h[p * HID + k] = make_float2(g, g);
        }
    }
    __syncthreads();

    // ---- main GEMM loop: acc[pp][c] (f32x2) += h[p][k] * w2[k][2q:2q+2] ----
    const int my = tid >> 5;   // warp -> 8-point group
    const int nx = tid & 31;   // lane -> d-pair base

    unsigned long long acc[8][8];
    #pragma unroll
    for (int pp = 0; pp < 8; pp++)
        #pragma unroll
        for (int c = 0; c < 8; c++) acc[pp][c] = 0ull;

    const unsigned long long* sh_h_u = (const unsigned long long*)sh_h;

    #pragma unroll 4
    for (int k = 0; k < HID; k++) {
        unsigned long long wv[8], h2[8];
        const unsigned long long* wk = (const unsigned long long*)(sh_w2 + k * DIM);
        #pragma unroll
        for (int c = 0; c < 8; c++) wv[c] = wk[nx + 32 * c];      // LDS.64 coalesced
        #pragma unroll
        for (int pp = 0; pp < 8; pp++)
            h2[pp] = sh_h_u[(my * 8 + pp) * HID + k];             // LDS.64 broadcast {h,h}
        #pragma unroll
        for (int pp = 0; pp < 8; pp++)
            #pragma unroll
            for (int c = 0; c < 8; c++)
                asm("fma.rn.f32x2 %0, %1, %2, %3;"
                    : "=l"(acc[pp][c])
                    : "l"(h2[pp]), "l"(wv[c]), "l"(acc[pp][c]));
    }

    // ---- epilogue: bilinear + b2 + mask, write out ----
    #pragma unroll
    for (int pp = 0; pp < 8; pp++) {
        int p = my * 8 + pp;
        int i = i0 + (p >> 5);
        int j = p & 31;
        bool msk = (i < H) && (j < W);

        float u = (H > 1) ? (float)i / (float)(H - 1) : 0.0f;
        float v = (W > 1) ? (float)j / (float)(W - 1) : 0.0f;
        float sy = fminf(u * (float)(SGRID - 1), (float)(SGRID - 1));
        float sx = fminf(v * (float)(SGRID - 1), (float)(SGRID - 1));
        int y0 = (int)sy;                 // sy >= 0
        int x0 = (int)sx;
        float wy = sy - (float)y0;
        float wx = sx - (float)x0;
        int y1 = min(y0 + 1, SGRID - 1);
        int x1 = min(x0 + 1, SGRID - 1);
        float wyc = 1.0f - wy, wxc = 1.0f - wx;

        const float* c00 = canonical + (y0 * SGRID + x0) * DIM;
        const float* c01 = canonical + (y0 * SGRID + x1) * DIM;
        const float* c10 = canonical + (y1 * SGRID + x0) * DIM;
        const float* c11 = canonical + (y1 * SGRID + x1) * DIM;

        size_t obase = ((size_t)(((bb << 6) + i) * 32 + j)) * DIM;

        #pragma unroll
        for (int c = 0; c < 8; c++) {
            int d0 = (nx + 32 * c) * 2;
            float2 q00 = __ldg((const float2*)(c00 + d0));
            float2 q01 = __ldg((const float2*)(c01 + d0));
            float2 q10 = __ldg((const float2*)(c10 + d0));
            float2 q11 = __ldg((const float2*)(c11 + d0));
            float2 bv  = __ldg((const float2*)(b2 + d0));

            float bilx = wyc * (wxc * q00.x + wx * q01.x) + wy * (wxc * q10.x + wx * q11.x);
            float bily = wyc * (wxc * q00.y + wx * q01.y) + wy * (wxc * q10.y + wx * q11.y);

            unsigned long long a = acc[pp][c];
            float ax = __uint_as_float((unsigned int)a);
            float ay = __uint_as_float((unsigned int)(a >> 32));

            float2 r;
            r.x = msk ? (bilx + ax + bv.x) : 0.0f;
            r.y = msk ? (bily + ay + bv.y) : 0.0f;
            *(float2*)(out + obase + d0) = r;
        }
    }
}

// Mask tail (only launched if out_size > queries size). Writes mask as
// 1.0f/0.0f, zero-fills any extra padding.
__global__ void hgq_mask(const int* __restrict__ th, const int* __restrict__ tw,
                         float* __restrict__ outt, int tail)
{
    int idx = blockIdx.x * 256 + threadIdx.x;
    if (idx >= tail) return;
    float val = 0.0f;
    if (idx < BATCH * MAXH * MAXW) {
        int bb = idx >> 11;
        int r  = idx & 2047;
        int i  = r >> 5;
        int j  = r & 31;
        int H = min(max(th[bb], 1), MAXH);
        int W = min(max(tw[bb], 1), MAXW);
        val = (i < H && j < W) ? 1.0f : 0.0f;
    }
    outt[idx] = val;
}

extern "C" void kernel_launch(void* const* d_in, const int* in_sizes, int n_in,
                              void* d_out, int out_size)
{
    // metadata order: canonical, w1, b1, w2, b2, batch_size, target_h_list,
    //                 target_w_list, max_h, max_w
    const float* canonical = (const float*)d_in[0];
    const float* w1        = (const float*)d_in[1];
    const float* b1        = (const float*)d_in[2];
    const float* w2        = (const float*)d_in[3];
    const float* b2        = (const float*)d_in[4];
    const int*   th        = (const int*)d_in[6];
    const int*   tw        = (const int*)d_in[7];
    float* out = (float*)d_out;

    cudaFuncSetAttribute(hgq_main, cudaFuncAttributeMaxDynamicSharedMemorySize, SMEM_BYTES);
    hgq_main<<<NTILES, TPB, SMEM_BYTES>>>(canonical, w1, b1, w2, b2, th, tw, out);

    const int qelems = BATCH * MAXH * MAXW * DIM;   // 67108864
    int tail = out_size - qelems;
    if (tail > 0) {
        hgq_mask<<<(tail + 255) / 256, 256>>>(th, tw, out + qelems, tail);
    }
}